// round 16
// baseline (speedup 1.0000x reference)
#include <cuda_runtime.h>
#include <cstdint>

// CausalWindowedAttention: B=2,H=16,S=2048,D=64, window=256, temp=8
// Output = concat(out[B,H,S,D], attn[B,H,S,S]) as float32.
// Round-15 structure + K loads software-pipelined through the QK dc-loop in
// 4 column-chunks (cp.async issue gaps filled by previous chunk's FFMA2).
// Warp-local tail: epilogue + band TMA + PV per warp; V single dense bulk.

#define SQ    2048
#define DH    64
#define MT    64              // queries per CTA tile
#define WIN   256
#define KRA   320             // key rows resident (reads clamped to row 319)
#define KPAD  68              // padded K row (floats), conflict-free LDS.128
#define SROW  268             // score row stride: 4 slack + up to 264 offsets
#define NTH   512

// smem layout (floats)
#define SM_Q   0
#define SM_K   (MT * DH)                  // 4096  (K padded; V dense alias)
#define SM_S   (SM_K + KRA * KPAD)        // 25856
#define SM_Z   (SM_S + MT * SROW)         // 43008
#define SM_MB  (SM_Z + 2048)              // 45056 (8B-aligned mbarrier)
#define SM_TOT (SM_MB + 4)                // 45060 floats = 180240 B

typedef unsigned long long ull;

__device__ __forceinline__ void ffma2(ull& d, ull a, ull b) {
    asm("fma.rn.f32x2 %0, %1, %2, %0;" : "+l"(d) : "l"(a), "l"(b));
}
__device__ __forceinline__ ull pk2(float x) {
    ull r;
    asm("mov.b64 %0, {%1, %1};" : "=l"(r) : "f"(x));
    return r;
}
__device__ __forceinline__ float unpk_sum(ull a) {
    float lo, hi;
    asm("mov.b64 {%0, %1}, %2;" : "=f"(lo), "=f"(hi) : "l"(a));
    return lo + hi;
}
__device__ __forceinline__ uint32_t s2u(const void* p) {
    return (uint32_t)__cvta_generic_to_shared(p);
}
__device__ __forceinline__ void bulk_store(void* gdst, uint32_t ssrc, uint32_t bytes) {
    asm volatile("cp.async.bulk.global.shared::cta.bulk_group [%0], [%1], %2;"
                 :: "l"(gdst), "r"(ssrc), "r"(bytes) : "memory");
}
__device__ __forceinline__ void bulk_load(uint32_t sdst, const void* gsrc,
                                          uint32_t bytes, uint32_t mbar) {
    asm volatile("cp.async.bulk.shared::cluster.global.mbarrier::complete_tx::bytes "
                 "[%0], [%1], %2, [%3];"
                 :: "r"(sdst), "l"(gsrc), "r"(bytes), "r"(mbar) : "memory");
}
__device__ __forceinline__ void fence_async() {
    asm volatile("fence.proxy.async.shared::cta;" ::: "memory");
}
__device__ __forceinline__ void cp16(uint32_t sdst, const void* gsrc, uint32_t sz) {
    asm volatile("cp.async.cg.shared.global [%0], [%1], 16, %2;"
                 :: "r"(sdst), "l"(gsrc), "r"(sz) : "memory");
}
__device__ __forceinline__ void cp_commit() {
    asm volatile("cp.async.commit_group;" ::: "memory");
}
template<int N>
__device__ __forceinline__ void cp_wait_n() {
    asm volatile("cp.async.wait_group %0;" :: "n"(N) : "memory");
}
__device__ __forceinline__ void mbar_init(uint32_t mbar, uint32_t cnt) {
    asm volatile("mbarrier.init.shared.b64 [%0], %1;" :: "r"(mbar), "r"(cnt) : "memory");
}
__device__ __forceinline__ void mbar_arrive_expect(uint32_t mbar, uint32_t bytes) {
    asm volatile("mbarrier.arrive.expect_tx.shared.b64 _, [%0], %1;"
                 :: "r"(mbar), "r"(bytes) : "memory");
}
__device__ __forceinline__ void mbar_wait(uint32_t mbar, uint32_t parity) {
    uint32_t done = 0;
    while (!done) {
        asm volatile(
            "{\n\t.reg .pred p;\n\t"
            "mbarrier.try_wait.parity.shared.b64 p, [%1], %2;\n\t"
            "selp.b32 %0, 1, 0, p;\n\t}"
            : "=r"(done) : "r"(mbar), "r"(parity) : "memory");
    }
}

__global__ void __launch_bounds__(NTH, 1)
cwa_kernel(const float* __restrict__ q,
           const float* __restrict__ k,
           const float* __restrict__ v,
           float* __restrict__ out,    // [BH, SQ, DH]
           float* __restrict__ attn)   // [BH, SQ, SQ]
{
    extern __shared__ float sm[];
    float* sQ = sm + SM_Q;   // Q tile; reused as out-tile staging for TMA
    float* sK = sm + SM_K;   // K tile (padded); reused for V (DENSE, stride 64)
    float* sS = sm + SM_S;   // 64 rows x SROW; row m offsets indexed [-4, 264)
    float* sZ = sm + SM_Z;   // 2048 zero floats
    const uint32_t mb = s2u(sm + SM_MB);

    const int tile = blockIdx.x;
    const int bh   = blockIdx.y;
    const int i0   = tile * MT;
    const int tid  = threadIdx.x;
    const int lane = tid & 31;
    const int w    = tid >> 5;           // 0..15

    const size_t base = (size_t)bh * SQ * DH;
    const size_t attn_base = (size_t)bh * SQ * SQ;
    const int jn0 = i0 - (WIN - 1);      // key j for smem key-row n: j = jn0 + n

    // key rows with valid gmem backing: n in [n_lo, n_hi)
    const int n_lo = max(0, -jn0);
    const int n_hi = min(KRA, SQ - jn0);

    // ---- mbarrier init ----
    if (tid == 0)
        mbar_init(mb, 1);

    // K column-chunk issue: chunk ch covers dc columns 4ch..4ch+3
    // (bytes 16*(4ch) .. of each padded row). 1280 cp.async ops per chunk.
    auto issue_k_chunk = [&](int ch) {
        const int c0 = ch * 4;
        for (int idx = tid; idx < KRA * 4; idx += NTH) {
            int n = idx >> 2;
            int cc = (idx & 3) + c0;
            int j = jn0 + n;
            bool valid = (j >= 0 && j < SQ);
            const float* src = valid ? (k + base + (size_t)j * DH + cc * 4)
                                     : (k + base);
            cp16(s2u(&sK[n * KPAD + cc * 4]), src, valid ? 16u : 0u);
        }
        cp_commit();
    };

    // ---- chunk 0 of K first: it gates the QK loop ----
    issue_k_chunk(0);

    // ---- zero buffer (TMA zero-store source) ----
    {
        const float4 z4 = make_float4(0.f, 0.f, 0.f, 0.f);
        float4* zs = (float4*)sZ;
        for (int idx = tid; idx < 2048 / 4; idx += NTH)
            zs[idx] = z4;
    }
    __syncthreads();    // mbarrier + sZ visible CTA-wide

    // ---- Q: one 16KB bulk load (mbarrier phase 0) ----
    if (tid == 0) {
        mbar_arrive_expect(mb, (uint32_t)(MT * DH * 4));
        bulk_load(s2u(sQ), q + base + (size_t)i0 * DH,
                  (uint32_t)(MT * DH * 4), mb);
    }

    // ---- merged zero bulk stores: suffix(i)+prefix(i+1) contiguous, 65 ops ----
    if (tid < MT) {
        const int m = tid;
        const int i = i0 + m;
        const int jlo = max(0, i - (WIN - 1));
        const int jstart4 = jlo & ~3;
        const int jend4 = (i + 4) & ~3;           // exclusive, multiple of 4
        float* row = attn + attn_base + (size_t)i * SQ;
        const uint32_t zaddr = s2u(sZ);
        fence_async();
        if (m == 0) {                              // first row's own prefix
            const uint32_t pb = (uint32_t)jstart4 * 4u;
            if (pb) bulk_store(row, zaddr, pb);
        }
        if (m < MT - 1) {                          // suffix(i) + prefix(i+1)
            const int jstart4_n = (max(0, i + 1 - (WIN - 1))) & ~3;
            const uint32_t bytes = (uint32_t)(SQ - jend4 + jstart4_n) * 4u;
            if (bytes) bulk_store(row + jend4, zaddr, bytes);
        } else {                                   // last row: suffix only
            const uint32_t sb = (uint32_t)(SQ - jend4) * 4u;
            if (sb) bulk_store(row + jend4, zaddr, sb);
        }
    }

    mbar_wait(mb, 0);   // Q resident (chunk 0 K gated inside the loop)

    // ---- QK, pipelined over 4 K column-chunks ----
    const int m0 = w * 4;
    ull acc[4][9];
    {
        #pragma unroll
        for (int mi = 0; mi < 4; mi++)
            #pragma unroll
            for (int ni = 0; ni < 9; ni++)
                acc[mi][ni] = 0ULL;

        int nb[9];
        #pragma unroll
        for (int ni = 0; ni < 9; ni++)
            nb[ni] = min(m0 + lane + 32 * ni, KRA - 1) * KPAD;  // clamp masked tail

        #pragma unroll
        for (int ch = 0; ch < 4; ch++) {
            // issue next chunk; its LDGSTS acceptance gaps are filled by
            // this chunk's FFMA2 (other warps / following instructions)
            if (ch < 3) {
                issue_k_chunk(ch + 1);
                cp_wait_n<1>();        // all but the newest group resident
            } else {
                cp_wait_n<0>();        // everything resident
            }
            __syncthreads();           // other threads' chunk stores visible

            #pragma unroll 1
            for (int dci = 0; dci < 4; dci++) {
                const int dc = ch * 4 + dci;
                ulonglong2 q2[4];
                #pragma unroll
                for (int mi = 0; mi < 4; mi++)
                    q2[mi] = *(const ulonglong2*)&sQ[(m0 + mi) * DH + dc * 4];
                // chunk 1: groups 0..3 (limits live k2 regs)
                {
                    ulonglong2 k2[4];
                    #pragma unroll
                    for (int ni = 0; ni < 4; ni++)
                        k2[ni] = *(const ulonglong2*)&sK[nb[ni] + dc * 4];
                    #pragma unroll
                    for (int ni = 0; ni < 4; ni++)
                        #pragma unroll
                        for (int mi = 0; mi < 4; mi++) {
                            ffma2(acc[mi][ni], q2[mi].x, k2[ni].x);
                            ffma2(acc[mi][ni], q2[mi].y, k2[ni].y);
                        }
                }
                // chunk 2: groups 4..8
                {
                    ulonglong2 k2[5];
                    #pragma unroll
                    for (int ni = 0; ni < 5; ni++)
                        k2[ni] = *(const ulonglong2*)&sK[nb[ni + 4] + dc * 4];
                    #pragma unroll
                    for (int ni = 0; ni < 5; ni++)
                        #pragma unroll
                        for (int mi = 0; mi < 4; mi++) {
                            ffma2(acc[mi][ni + 4], q2[mi].x, k2[ni].x);
                            ffma2(acc[mi][ni + 4], q2[mi].y, k2[ni].y);
                        }
                }
            }
        }
    }
    __syncthreads();   // all QK reads of sK AND sQ done (acc in registers)

    // ---- V: ONE dense bulk load into sK region (phase 1).
    //      Rows n_lo..n_hi-1 contiguous in gmem. Rows < n_lo alias bytes
    //      already written by the padded-K fill (finite), and p=0 there,
    //      so no zeroing is needed (0 * finite = 0).
    if (tid == 0) {
        mbar_arrive_expect(mb, (uint32_t)(n_hi - n_lo) * (DH * 4));
        bulk_load(s2u(&sK[n_lo * DH]),
                  v + base + (size_t)(jn0 + n_lo) * DH,
                  (uint32_t)(n_hi - n_lo) * (DH * 4), mb);
    }

    // ---- epilogue: fixed-shift exp, sum, store p; self-zeroes the row ----
    {
        #pragma unroll
        for (int mi = 0; mi < 4; mi++) {
            const int m = m0 + mi;
            const int i = i0 + m;
            const int jlo = max(0, i - (WIN - 1));
            const int s = (jlo & ~3) - jn0;
            const int off_lo = jlo & 3;
            const int off_hi = i - (jlo & ~3);
            float* rp = sS + m * SROW + 4;

            // head slack [-4, m0-s): stores below cover from max(-4, m0-s)
            const int cnt = min(max(m0 - s + 4, 0), 8);
            if (lane < cnt)
                rp[-4 + lane] = 0.f;

            float sc[9];
            float sum = 0.f;
            #pragma unroll
            for (int ni = 0; ni < 9; ni++) {
                const int off = m0 + lane + 32 * ni - s;
                const bool ok = (off >= off_lo) && (off <= off_hi);
                float e = ok ? __expf(unpk_sum(acc[mi][ni]) * 0.125f) : 0.f;
                sc[ni] = e;
                sum += e;
            }
            #pragma unroll
            for (int o = 16; o; o >>= 1)
                sum += __shfl_xor_sync(0xffffffffu, sum, o);

            const float inv = 1.f / sum;
            #pragma unroll
            for (int ni = 0; ni < 9; ni++) {
                const int off = m0 + lane + 32 * ni - s;
                // stores zeros outside the band too: covers [max(-4,m0-s), 263]
                if ((unsigned)(off + 4) < (unsigned)SROW)
                    rp[off] = sc[ni] * inv;
            }
        }
    }

    // ---- band bulk stores: warp-local rows, issue immediately ----
    __syncwarp();
    if (lane < 4) {
        const int m = m0 + lane;
        const int i = i0 + m;
        const int jlo = max(0, i - (WIN - 1));
        const int jstart4 = jlo & ~3;
        const int jend4 = (i + 4) & ~3;
        fence_async();
        bulk_store(attn + attn_base + (size_t)i * SQ + jstart4,
                   s2u(sS + m * SROW + 4),
                   (uint32_t)(jend4 - jstart4) * 4u);
    }

    mbar_wait(mb, 1);  // V resident (per-warp wait; p rows are warp-local)

    // ---- PV: warp-local. Warp w, rows r0=4w..4w+3; lane = dq + 16*kh ----
    {
        const int dq = lane & 15;         // d cols dq*4..dq*4+3
        const int kh = lane >> 4;         // key half within the warp
        const int r0 = m0;                // same rows as this warp's epilogue

        int sr[4];
        #pragma unroll
        for (int rr = 0; rr < 4; rr++)
            sr[rr] = (max(0, i0 + r0 + rr - (WIN - 1)) & ~3) - jn0;

        const int nbase = sr[3] - 4;            // ≡ 3 mod 4; aligned p4 loads
        const int nend  = r0 + 258;             // inclusive
        const int iters = (nend - nbase + 1) >> 2;
        const int ih    = (iters + 1) >> 1;
        const int itlo  = kh ? ih : 0;
        const int ithi  = kh ? iters : ih;

        const float* rp0 = sS + (r0 + 0) * SROW + 4 - sr[0];
        const float* rp1 = sS + (r0 + 1) * SROW + 4 - sr[1];
        const float* rp2 = sS + (r0 + 2) * SROW + 4 - sr[2];
        const float* rp3 = sS + (r0 + 3) * SROW + 4 - sr[3];

        ull ax[4], az[4];
        #pragma unroll
        for (int rr = 0; rr < 4; rr++) { ax[rr] = 0ULL; az[rr] = 0ULL; }

        #pragma unroll 1
        for (int it = itlo; it < ithi; it++) {
            const int n = nbase + 4 * it;
            const float4 p0 = *(const float4*)&rp0[n];
            const float4 p1 = *(const float4*)&rp1[n];
            const float4 p2 = *(const float4*)&rp2[n];
            const float4 p3 = *(const float4*)&rp3[n];
            #pragma unroll
            for (int c = 0; c < 4; c++) {
                ulonglong2 v2 = *(const ulonglong2*)&sK[(n + c) * DH + dq * 4];
                ull pc0 = pk2((&p0.x)[c]);
                ull pc1 = pk2((&p1.x)[c]);
                ull pc2 = pk2((&p2.x)[c]);
                ull pc3 = pk2((&p3.x)[c]);
                ffma2(ax[0], pc0, v2.x); ffma2(az[0], pc0, v2.y);
                ffma2(ax[1], pc1, v2.x); ffma2(az[1], pc1, v2.y);
                ffma2(ax[2], pc2, v2.x); ffma2(az[2], pc2, v2.y);
                ffma2(ax[3], pc3, v2.x); ffma2(az[3], pc3, v2.y);
            }
        }

        // combine key halves across lane-16 pairs via shfl; lanes<16 stage
        // the out tile into sQ (Q fully consumed by QK).
        #pragma unroll
        for (int rr = 0; rr < 4; rr++) {
            float f0, f1, f2, f3;
            asm("mov.b64 {%0, %1}, %2;" : "=f"(f0), "=f"(f1) : "l"(ax[rr]));
            asm("mov.b64 {%0, %1}, %2;" : "=f"(f2), "=f"(f3) : "l"(az[rr]));
            f0 += __shfl_xor_sync(0xffffffffu, f0, 16);
            f1 += __shfl_xor_sync(0xffffffffu, f1, 16);
            f2 += __shfl_xor_sync(0xffffffffu, f2, 16);
            f3 += __shfl_xor_sync(0xffffffffu, f3, 16);
            if (kh == 0)
                *(float4*)&sQ[(r0 + rr) * DH + dq * 4] =
                    make_float4(f0, f1, f2, f3);
        }
    }
    __syncthreads();   // full out tile staged in sQ

    // ---- out tile: one 16KB bulk store (contiguous [64][64] in gmem) ----
    if (tid == 0) {
        fence_async();
        bulk_store(out + base + (size_t)i0 * DH, s2u(sQ),
                   (uint32_t)(MT * DH * 4));
    }

    // ---- ensure all bulk stores complete before kernel end ----
    asm volatile("cp.async.bulk.commit_group;" ::: "memory");
    asm volatile("cp.async.bulk.wait_group 0;" ::: "memory");
}

extern "C" void kernel_launch(void* const* d_in, const int* in_sizes, int n_in,
                              void* d_out, int out_size)
{
    const float* q = (const float*)d_in[0];
    const float* k = (const float*)d_in[1];
    const float* v = (const float*)d_in[2];

    const int BH = in_sizes[0] / (SQ * DH);   // 32

    float* out  = (float*)d_out;
    float* attn = out + (size_t)BH * SQ * DH;

    cudaFuncSetAttribute(cwa_kernel,
                         cudaFuncAttributeMaxDynamicSharedMemorySize,
                         SM_TOT * (int)sizeof(float));

    dim3 grid(SQ / MT, BH);
    cwa_kernel<<<grid, NTH, SM_TOT * sizeof(float)>>>(q, k, v, out, attn);
    (void)n_in; (void)out_size;
}

// round 17
// speedup vs baseline: 1.1026x; 1.1026x over previous
#include <cuda_runtime.h>
#include <cstdint>

// CausalWindowedAttention: B=2,H=16,S=2048,D=64, window=256, temp=8
// Output = concat(out[B,H,S,D], attn[B,H,S,S]) as float32.
// Round-15 structure with K stored DENSE and loaded via ONE cp.async.bulk:
// QK avoids bank conflicts by lane-rotating the d-walk (dc = (dci+lane)&15),
// exploiting dot-product order invariance. Warp-local tail: epilogue + band
// TMA + PV per warp; V single dense bulk load into the same buffer.

#define SQ    2048
#define DH    64
#define MT    64              // queries per CTA tile
#define WIN   256
#define KRA   320             // key rows resident (reads clamped to row 319)
#define SROW  268             // score row stride: 4 slack + up to 264 offsets
#define NTH   512

// smem layout (floats)
#define SM_Q   0
#define SM_K   (MT * DH)                  // 4096  (K dense; V dense alias)
#define SM_S   (SM_K + KRA * DH)          // 24576
#define SM_Z   (SM_S + MT * SROW)         // 41728
#define SM_MB  (SM_Z + 2048)              // 43776 (8B-aligned mbarrier)
#define SM_TOT (SM_MB + 4)                // 43780 floats = 175120 B

typedef unsigned long long ull;

__device__ __forceinline__ void ffma2(ull& d, ull a, ull b) {
    asm("fma.rn.f32x2 %0, %1, %2, %0;" : "+l"(d) : "l"(a), "l"(b));
}
__device__ __forceinline__ ull pk2(float x) {
    ull r;
    asm("mov.b64 %0, {%1, %1};" : "=l"(r) : "f"(x));
    return r;
}
__device__ __forceinline__ float unpk_sum(ull a) {
    float lo, hi;
    asm("mov.b64 {%0, %1}, %2;" : "=f"(lo), "=f"(hi) : "l"(a));
    return lo + hi;
}
__device__ __forceinline__ uint32_t s2u(const void* p) {
    return (uint32_t)__cvta_generic_to_shared(p);
}
__device__ __forceinline__ void bulk_store(void* gdst, uint32_t ssrc, uint32_t bytes) {
    asm volatile("cp.async.bulk.global.shared::cta.bulk_group [%0], [%1], %2;"
                 :: "l"(gdst), "r"(ssrc), "r"(bytes) : "memory");
}
__device__ __forceinline__ void bulk_load(uint32_t sdst, const void* gsrc,
                                          uint32_t bytes, uint32_t mbar) {
    asm volatile("cp.async.bulk.shared::cluster.global.mbarrier::complete_tx::bytes "
                 "[%0], [%1], %2, [%3];"
                 :: "r"(sdst), "l"(gsrc), "r"(bytes), "r"(mbar) : "memory");
}
__device__ __forceinline__ void fence_async() {
    asm volatile("fence.proxy.async.shared::cta;" ::: "memory");
}
__device__ __forceinline__ void mbar_init(uint32_t mbar, uint32_t cnt) {
    asm volatile("mbarrier.init.shared.b64 [%0], %1;" :: "r"(mbar), "r"(cnt) : "memory");
}
__device__ __forceinline__ void mbar_arrive_expect(uint32_t mbar, uint32_t bytes) {
    asm volatile("mbarrier.arrive.expect_tx.shared.b64 _, [%0], %1;"
                 :: "r"(mbar), "r"(bytes) : "memory");
}
__device__ __forceinline__ void mbar_wait(uint32_t mbar, uint32_t parity) {
    uint32_t done = 0;
    while (!done) {
        asm volatile(
            "{\n\t.reg .pred p;\n\t"
            "mbarrier.try_wait.parity.shared.b64 p, [%1], %2;\n\t"
            "selp.b32 %0, 1, 0, p;\n\t}"
            : "=r"(done) : "r"(mbar), "r"(parity) : "memory");
    }
}

__global__ void __launch_bounds__(NTH, 1)
cwa_kernel(const float* __restrict__ q,
           const float* __restrict__ k,
           const float* __restrict__ v,
           float* __restrict__ out,    // [BH, SQ, DH]
           float* __restrict__ attn)   // [BH, SQ, SQ]
{
    extern __shared__ float sm[];
    float* sQ = sm + SM_Q;   // Q tile; reused as out-tile staging for TMA
    float* sK = sm + SM_K;   // K tile (DENSE, stride 64); reused for V (dense)
    float* sS = sm + SM_S;   // 64 rows x SROW; row m offsets indexed [-4, 264)
    float* sZ = sm + SM_Z;   // 2048 zero floats
    const uint32_t mb = s2u(sm + SM_MB);

    const int tile = blockIdx.x;
    const int bh   = blockIdx.y;
    const int i0   = tile * MT;
    const int tid  = threadIdx.x;
    const int lane = tid & 31;
    const int w    = tid >> 5;           // 0..15

    const size_t base = (size_t)bh * SQ * DH;
    const size_t attn_base = (size_t)bh * SQ * SQ;
    const int jn0 = i0 - (WIN - 1);      // key j for smem key-row n: j = jn0 + n

    // key rows with valid gmem backing: n in [n_lo, n_hi)
    const int n_lo = max(0, -jn0);
    const int n_hi = min(KRA, SQ - jn0);

    // ---- mbarrier init + zero buffer ----
    if (tid == 0)
        mbar_init(mb, 1);
    {
        const float4 z4 = make_float4(0.f, 0.f, 0.f, 0.f);
        float4* zs = (float4*)sZ;
        for (int idx = tid; idx < 2048 / 4; idx += NTH)
            zs[idx] = z4;
    }
    __syncthreads();    // mbarrier + sZ visible CTA-wide

    // ---- Q (16KB) + K window (dense, contiguous rows): bulk loads, phase 0 ----
    if (tid == 0) {
        mbar_arrive_expect(mb, (uint32_t)(MT * DH * 4)
                               + (uint32_t)(n_hi - n_lo) * (DH * 4));
        bulk_load(s2u(sQ), q + base + (size_t)i0 * DH,
                  (uint32_t)(MT * DH * 4), mb);
        bulk_load(s2u(&sK[n_lo * DH]),
                  k + base + (size_t)(jn0 + n_lo) * DH,
                  (uint32_t)(n_hi - n_lo) * (DH * 4), mb);
    }

    // ---- zero head key rows (n < n_lo, j < 0) of the dense buffer.
    //      QK discards them (mask), but PV's p*V needs finite V there and
    //      neither the K nor the V bulk load covers these rows.
    for (int idx = tid; idx < n_lo * DH; idx += NTH)
        sK[idx] = 0.f;

    // ---- merged zero bulk stores: suffix(i)+prefix(i+1) contiguous, 65 ops ----
    if (tid < MT) {
        const int m = tid;
        const int i = i0 + m;
        const int jlo = max(0, i - (WIN - 1));
        const int jstart4 = jlo & ~3;
        const int jend4 = (i + 4) & ~3;           // exclusive, multiple of 4
        float* row = attn + attn_base + (size_t)i * SQ;
        const uint32_t zaddr = s2u(sZ);
        fence_async();
        if (m == 0) {                              // first row's own prefix
            const uint32_t pb = (uint32_t)jstart4 * 4u;
            if (pb) bulk_store(row, zaddr, pb);
        }
        if (m < MT - 1) {                          // suffix(i) + prefix(i+1)
            const int jstart4_n = (max(0, i + 1 - (WIN - 1))) & ~3;
            const uint32_t bytes = (uint32_t)(SQ - jend4 + jstart4_n) * 4u;
            if (bytes) bulk_store(row + jend4, zaddr, bytes);
        } else {                                   // last row: suffix only
            const uint32_t sb = (uint32_t)(SQ - jend4) * 4u;
            if (sb) bulk_store(row + jend4, zaddr, sb);
        }
    }

    mbar_wait(mb, 0);   // Q + K resident
    __syncthreads();    // head-row zeros visible too

    // ---- QK: warp w -> rows m0..m0+3, keys n = m0 + lane + 32*ni.
    //      Lane-rotated d-walk: dc = (dci + lane) & 15 makes dense-K reads
    //      conflict-free (8 consecutive lanes hit 8 distinct bank groups).
    const int m0 = w * 4;
    ull acc[4][9];
    {
        #pragma unroll
        for (int mi = 0; mi < 4; mi++)
            #pragma unroll
            for (int ni = 0; ni < 9; ni++)
                acc[mi][ni] = 0ULL;

        int nb[9];
        #pragma unroll
        for (int ni = 0; ni < 9; ni++)
            nb[ni] = min(m0 + lane + 32 * ni, KRA - 1) * DH;  // clamp masked tail

        #pragma unroll 1
        for (int dci = 0; dci < DH / 4; dci++) {
            const int dc4 = ((dci + lane) & 15) << 2;   // rotated d-offset
            ulonglong2 q2[4];
            #pragma unroll
            for (int mi = 0; mi < 4; mi++)
                q2[mi] = *(const ulonglong2*)&sQ[(m0 + mi) * DH + dc4];
            // chunk 1: groups 0..3 (limits live k2 regs)
            {
                ulonglong2 k2[4];
                #pragma unroll
                for (int ni = 0; ni < 4; ni++)
                    k2[ni] = *(const ulonglong2*)&sK[nb[ni] + dc4];
                #pragma unroll
                for (int ni = 0; ni < 4; ni++)
                    #pragma unroll
                    for (int mi = 0; mi < 4; mi++) {
                        ffma2(acc[mi][ni], q2[mi].x, k2[ni].x);
                        ffma2(acc[mi][ni], q2[mi].y, k2[ni].y);
                    }
            }
            // chunk 2: groups 4..8
            {
                ulonglong2 k2[5];
                #pragma unroll
                for (int ni = 0; ni < 5; ni++)
                    k2[ni] = *(const ulonglong2*)&sK[nb[ni + 4] + dc4];
                #pragma unroll
                for (int ni = 0; ni < 5; ni++)
                    #pragma unroll
                    for (int mi = 0; mi < 4; mi++) {
                        ffma2(acc[mi][ni + 4], q2[mi].x, k2[ni].x);
                        ffma2(acc[mi][ni + 4], q2[mi].y, k2[ni].y);
                    }
            }
        }
    }
    __syncthreads();   // all QK reads of sK AND sQ done (acc in registers)

    // ---- V: ONE dense bulk load into sK region (phase 1).
    //      Rows n_lo..n_hi-1 contiguous in gmem. Rows < n_lo stay zeroed
    //      from the head-zero pass (QK didn't write sK).
    if (tid == 0) {
        mbar_arrive_expect(mb, (uint32_t)(n_hi - n_lo) * (DH * 4));
        bulk_load(s2u(&sK[n_lo * DH]),
                  v + base + (size_t)(jn0 + n_lo) * DH,
                  (uint32_t)(n_hi - n_lo) * (DH * 4), mb);
    }

    // ---- epilogue: fixed-shift exp, sum, store p; self-zeroes the row ----
    {
        #pragma unroll
        for (int mi = 0; mi < 4; mi++) {
            const int m = m0 + mi;
            const int i = i0 + m;
            const int jlo = max(0, i - (WIN - 1));
            const int s = (jlo & ~3) - jn0;
            const int off_lo = jlo & 3;
            const int off_hi = i - (jlo & ~3);
            float* rp = sS + m * SROW + 4;

            // head slack [-4, m0-s): stores below cover from max(-4, m0-s)
            const int cnt = min(max(m0 - s + 4, 0), 8);
            if (lane < cnt)
                rp[-4 + lane] = 0.f;

            float sc[9];
            float sum = 0.f;
            #pragma unroll
            for (int ni = 0; ni < 9; ni++) {
                const int off = m0 + lane + 32 * ni - s;
                const bool ok = (off >= off_lo) && (off <= off_hi);
                float e = ok ? __expf(unpk_sum(acc[mi][ni]) * 0.125f) : 0.f;
                sc[ni] = e;
                sum += e;
            }
            #pragma unroll
            for (int o = 16; o; o >>= 1)
                sum += __shfl_xor_sync(0xffffffffu, sum, o);

            const float inv = 1.f / sum;
            #pragma unroll
            for (int ni = 0; ni < 9; ni++) {
                const int off = m0 + lane + 32 * ni - s;
                // stores zeros outside the band too: covers [max(-4,m0-s), 263]
                if ((unsigned)(off + 4) < (unsigned)SROW)
                    rp[off] = sc[ni] * inv;
            }
        }
    }

    // ---- band bulk stores: warp-local rows, issue immediately ----
    __syncwarp();
    if (lane < 4) {
        const int m = m0 + lane;
        const int i = i0 + m;
        const int jlo = max(0, i - (WIN - 1));
        const int jstart4 = jlo & ~3;
        const int jend4 = (i + 4) & ~3;
        fence_async();
        bulk_store(attn + attn_base + (size_t)i * SQ + jstart4,
                   s2u(sS + m * SROW + 4),
                   (uint32_t)(jend4 - jstart4) * 4u);
    }

    mbar_wait(mb, 1);  // V resident (per-warp wait; p rows are warp-local)

    // ---- PV: warp-local. Warp w, rows r0=4w..4w+3; lane = dq + 16*kh ----
    {
        const int dq = lane & 15;         // d cols dq*4..dq*4+3
        const int kh = lane >> 4;         // key half within the warp
        const int r0 = m0;                // same rows as this warp's epilogue

        int sr[4];
        #pragma unroll
        for (int rr = 0; rr < 4; rr++)
            sr[rr] = (max(0, i0 + r0 + rr - (WIN - 1)) & ~3) - jn0;

        const int nbase = sr[3] - 4;            // ≡ 3 mod 4; aligned p4 loads
        const int nend  = r0 + 258;             // inclusive
        const int iters = (nend - nbase + 1) >> 2;
        const int ih    = (iters + 1) >> 1;
        const int itlo  = kh ? ih : 0;
        const int ithi  = kh ? iters : ih;

        const float* rp0 = sS + (r0 + 0) * SROW + 4 - sr[0];
        const float* rp1 = sS + (r0 + 1) * SROW + 4 - sr[1];
        const float* rp2 = sS + (r0 + 2) * SROW + 4 - sr[2];
        const float* rp3 = sS + (r0 + 3) * SROW + 4 - sr[3];

        ull ax[4], az[4];
        #pragma unroll
        for (int rr = 0; rr < 4; rr++) { ax[rr] = 0ULL; az[rr] = 0ULL; }

        #pragma unroll 1
        for (int it = itlo; it < ithi; it++) {
            const int n = nbase + 4 * it;
            const float4 p0 = *(const float4*)&rp0[n];
            const float4 p1 = *(const float4*)&rp1[n];
            const float4 p2 = *(const float4*)&rp2[n];
            const float4 p3 = *(const float4*)&rp3[n];
            #pragma unroll
            for (int c = 0; c < 4; c++) {
                ulonglong2 v2 = *(const ulonglong2*)&sK[(n + c) * DH + dq * 4];
                ull pc0 = pk2((&p0.x)[c]);
                ull pc1 = pk2((&p1.x)[c]);
                ull pc2 = pk2((&p2.x)[c]);
                ull pc3 = pk2((&p3.x)[c]);
                ffma2(ax[0], pc0, v2.x); ffma2(az[0], pc0, v2.y);
                ffma2(ax[1], pc1, v2.x); ffma2(az[1], pc1, v2.y);
                ffma2(ax[2], pc2, v2.x); ffma2(az[2], pc2, v2.y);
                ffma2(ax[3], pc3, v2.x); ffma2(az[3], pc3, v2.y);
            }
        }

        // combine key halves across lane-16 pairs via shfl; lanes<16 stage
        // the out tile into sQ (Q fully consumed by QK).
        #pragma unroll
        for (int rr = 0; rr < 4; rr++) {
            float f0, f1, f2, f3;
            asm("mov.b64 {%0, %1}, %2;" : "=f"(f0), "=f"(f1) : "l"(ax[rr]));
            asm("mov.b64 {%0, %1}, %2;" : "=f"(f2), "=f"(f3) : "l"(az[rr]));
            f0 += __shfl_xor_sync(0xffffffffu, f0, 16);
            f1 += __shfl_xor_sync(0xffffffffu, f1, 16);
            f2 += __shfl_xor_sync(0xffffffffu, f2, 16);
            f3 += __shfl_xor_sync(0xffffffffu, f3, 16);
            if (kh == 0)
                *(float4*)&sQ[(r0 + rr) * DH + dq * 4] =
                    make_float4(f0, f1, f2, f3);
        }
    }
    __syncthreads();   // full out tile staged in sQ

    // ---- out tile: one 16KB bulk store (contiguous [64][64] in gmem) ----
    if (tid == 0) {
        fence_async();
        bulk_store(out + base + (size_t)i0 * DH, s2u(sQ),
                   (uint32_t)(MT * DH * 4));
    }

    // ---- ensure all bulk stores complete before kernel end ----
    asm volatile("cp.async.bulk.commit_group;" ::: "memory");
    asm volatile("cp.async.bulk.wait_group 0;" ::: "memory");
}

extern "C" void kernel_launch(void* const* d_in, const int* in_sizes, int n_in,
                              void* d_out, int out_size)
{
    const float* q = (const float*)d_in[0];
    const float* k = (const float*)d_in[1];
    const float* v = (const float*)d_in[2];

    const int BH = in_sizes[0] / (SQ * DH);   // 32

    float* out  = (float*)d_out;
    float* attn = out + (size_t)BH * SQ * DH;

    cudaFuncSetAttribute(cwa_kernel,
                         cudaFuncAttributeMaxDynamicSharedMemorySize,
                         SM_TOT * (int)sizeof(float));

    dim3 grid(SQ / MT, BH);
    cwa_kernel<<<grid, NTH, SM_TOT * sizeof(float)>>>(q, k, v, out, attn);
    (void)n_in; (void)out_size;
}